// round 4
// baseline (speedup 1.0000x reference)
#include <cuda_runtime.h>
#include <cstdint>

// exp(X) for batched 32x32 symmetric fp32 via scaling-and-squaring, degree-8
// Paterson-Stockmeyer Taylor. TWO matrices per warp (half-warp h owns matrix h,
// lane owns columns jj and jj+16). Two smem buffers:
//   A: X -> X2s -> Z -> P (squaring chain)      E: Xs -> B2 -> V=B1+B2*Z
// mm B-operand columns are read from smem (lane-private, conflict-free), so
// only the 64-reg accumulator is live through most matmuls; one extra 64-reg
// array (B0 columns) persists through stages 1-3 only. Peak ~150 regs fits
// the 12-CTA/SM occupancy cap without spilling.

#define STRIDE 36               // floats per smem row (conflict-free, 16B aligned)
#define MOFF   1168             // matrix-1 offset inside a buffer (+16-bank shift)
#define BUFF   2320             // floats per buffer (2 matrices)

typedef unsigned long long u64;

__device__ __forceinline__ u64 pk2(float lo, float hi) {
    u64 r; asm("mov.b64 %0, {%1, %2};" : "=l"(r) : "f"(lo), "f"(hi)); return r;
}
__device__ __forceinline__ void upk2(float& lo, float& hi, u64 v) {
    asm("mov.b64 {%0, %1}, %2;" : "=f"(lo), "=f"(hi) : "l"(v));
}
__device__ __forceinline__ void fma2(u64& d, u64 a, u64 b) {
    asm("fma.rn.f32x2 %0, %1, %2, %0;" : "+l"(d) : "l"(a), "l"(b));
}
__device__ __forceinline__ u64 mul2(u64 a, u64 b) {
    u64 d; asm("mul.rn.f32x2 %0, %1, %2;" : "=l"(d) : "l"(a), "l"(b)); return d;
}
__device__ __forceinline__ float ldsf(uint32_t a) {
    float f; asm volatile("ld.shared.f32 %0, [%1];" : "=f"(f) : "r"(a)); return f;
}
__device__ __forceinline__ void stsf(uint32_t a, float f) {
    asm volatile("st.shared.f32 [%0], %1;" :: "r"(a), "f"(f));
}

// C(:,c0|c1) = A * B(:,c0|c1); A rows broadcast from smem (LDS.128, two
// half-warps hit bank-disjoint rows), B scalars read per-lane from smem.
__device__ __forceinline__ void mm_s(uint32_t aBase, uint32_t b0a, uint32_t b1a,
                                     u64 acc0[16], u64 acc1[16]) {
    {   // k = 0 peeled: mul instead of fma (no zero-init MOVs)
        float f0 = ldsf(b0a), f1 = ldsf(b1a);
        u64 bb0 = pk2(f0, f0), bb1 = pk2(f1, f1);
#pragma unroll
        for (int q = 0; q < 8; ++q) {
            u64 a0, a1;
            asm volatile("ld.shared.v2.u64 {%0, %1}, [%2];"
                         : "=l"(a0), "=l"(a1) : "r"(aBase + (uint32_t)(q * 16)));
            acc0[2 * q]     = mul2(a0, bb0);
            acc0[2 * q + 1] = mul2(a1, bb0);
            acc1[2 * q]     = mul2(a0, bb1);
            acc1[2 * q + 1] = mul2(a1, bb1);
        }
    }
#pragma unroll
    for (int k = 1; k < 32; ++k) {
        float f0 = ldsf(b0a + (uint32_t)(k * STRIDE * 4));
        float f1 = ldsf(b1a + (uint32_t)(k * STRIDE * 4));
        u64 bb0 = pk2(f0, f0), bb1 = pk2(f1, f1);
        uint32_t ra = aBase + (uint32_t)(k * STRIDE * 4);
#pragma unroll
        for (int q = 0; q < 8; ++q) {
            u64 a0, a1;
            asm volatile("ld.shared.v2.u64 {%0, %1}, [%2];"
                         : "=l"(a0), "=l"(a1) : "r"(ra + (uint32_t)(q * 16)));
            fma2(acc0[2 * q],     a0, bb0);
            fma2(acc0[2 * q + 1], a1, bb0);
            fma2(acc1[2 * q],     a0, bb1);
            fma2(acc1[2 * q + 1], a1, bb1);
        }
    }
}

__global__ void __launch_bounds__(32, 12)
ExpEig_52553219834314_kernel(const float* __restrict__ in,
                             float* __restrict__ out, int B) {
    __shared__ __align__(16) float smem[2 * BUFF];

    const int lane = threadIdx.x;
    const int h = lane >> 4, jj = lane & 15;
    int mat = blockIdx.x * 2 + h;
    const bool alive = (mat < B);
    if (!alive) mat = B - 1;
    const int c0 = jj, c1 = jj + 16;

    float* myA = smem + h * MOFF;
    float* myE = myA + BUFF;
    const uint32_t aA = (uint32_t)__cvta_generic_to_shared(myA);
    const uint32_t aE = aA + (uint32_t)(BUFF * 4);
    const uint32_t aAc0 = aA + (uint32_t)(c0 * 4), aAc1 = aA + (uint32_t)(c1 * 4);
    const uint32_t aEc0 = aE + (uint32_t)(c0 * 4), aEc1 = aE + (uint32_t)(c1 * 4);

    // Load X columns from gmem -> A (transient regs die immediately).
    {
        const float* src = in + (size_t)mat * 1024;
#pragma unroll
        for (int i = 0; i < 32; ++i) {
            stsf(aAc0 + (uint32_t)(i * STRIDE * 4), src[i * 32 + c0]);
            stsf(aAc1 + (uint32_t)(i * STRIDE * 4), src[i * 32 + c1]);
        }
    }
    __syncwarp();

    u64 acc0[16], acc1[16];
    float p0[32], p1[32];     // B0 columns (stages 1-3), then final result

    // ---- stage 0: X2 = X * X   (A-op = A = X, B-op = X cols from A)
    mm_s(aA, aAc0, aAc1, acc0, acc1);

    // Spectral bound: ||X||_2 <= sqrt(min(||X2||_1, ||X2||_F)).
    float rs, fb = 0.f;
    {
        float sa = 0.f, sb = 0.f;
#pragma unroll
        for (int p = 0; p < 16; ++p) {
            float t0, t1, u0, u1;
            upk2(t0, t1, acc0[p]); upk2(u0, u1, acc1[p]);
            sa += fabsf(t0) + fabsf(t1);
            sb += fabsf(u0) + fabsf(u1);
            fb += t0 * t0 + t1 * t1 + u0 * u0 + u1 * u1;
        }
        rs = fmaxf(sa, sb);
    }
#pragma unroll
    for (int off = 8; off > 0; off >>= 1) {
        rs = fmaxf(rs, __shfl_xor_sync(0xffffffffu, rs, off));
        fb += __shfl_xor_sync(0xffffffffu, fb, off);
    }
    float bnd = sqrtf(fminf(rs, sqrtf(fb)));
    bnd = fmaxf(bnd, __shfl_xor_sync(0xffffffffu, bnd, 16));
    int e = 0; (void)frexpf(bnd, &e);
    const int kk = e < 0 ? 0 : (e > 24 ? 24 : e);
    const int total = 4 + kk;
    const float s1 = exp2f(-(float)kk), s2 = s1 * s1;

    __syncwarp();   // stage-0 mm reads of A complete
    // E := Xs = s1 * X (read A cols);  A := X2s = s2 * X2 (from acc).
#pragma unroll
    for (int p = 0; p < 16; ++p) {
        const int i0 = 2 * p, i1 = 2 * p + 1;
        float x20, x21, x30, x31;
        upk2(x20, x21, acc0[p]); upk2(x30, x31, acc1[p]);
        stsf(aEc0 + (uint32_t)(i0 * STRIDE * 4), s1 * ldsf(aAc0 + (uint32_t)(i0 * STRIDE * 4)));
        stsf(aEc0 + (uint32_t)(i1 * STRIDE * 4), s1 * ldsf(aAc0 + (uint32_t)(i1 * STRIDE * 4)));
        stsf(aEc1 + (uint32_t)(i0 * STRIDE * 4), s1 * ldsf(aAc1 + (uint32_t)(i0 * STRIDE * 4)));
        stsf(aEc1 + (uint32_t)(i1 * STRIDE * 4), s1 * ldsf(aAc1 + (uint32_t)(i1 * STRIDE * 4)));
        stsf(aAc0 + (uint32_t)(i0 * STRIDE * 4), s2 * x20);
        stsf(aAc0 + (uint32_t)(i1 * STRIDE * 4), s2 * x21);
        stsf(aAc1 + (uint32_t)(i0 * STRIDE * 4), s2 * x30);
        stsf(aAc1 + (uint32_t)(i1 * STRIDE * 4), s2 * x31);
    }
    __syncwarp();

    // ---- stage 1: Z = Xs * X2s   (A-op = E = Xs, B-op = X2s cols from A)
    mm_s(aE, aAc0, aAc1, acc0, acc1);
    __syncwarp();   // mm reads of E (cross-lane) and A complete
    // p := B0 = I + Xs + X2s/2;  E := B2 = I/720 + Xs/5040 + X2s/40320;  A := Z.
#pragma unroll
    for (int p = 0; p < 16; ++p) {
        const int i0 = 2 * p, i1 = 2 * p + 1;
        float z00, z01, z10, z11;
        upk2(z00, z01, acc0[p]); upk2(z10, z11, acc1[p]);
        {
            float xs = ldsf(aEc0 + (uint32_t)(i0 * STRIDE * 4));
            float x2 = ldsf(aAc0 + (uint32_t)(i0 * STRIDE * 4));
            float kr = (i0 == c0) ? 1.f : 0.f;
            p0[i0] = kr + xs + 0.5f * x2;
            stsf(aEc0 + (uint32_t)(i0 * STRIDE * 4),
                 kr * (1.f / 720.f) + xs * (1.f / 5040.f) + x2 * (1.f / 40320.f));
            stsf(aAc0 + (uint32_t)(i0 * STRIDE * 4), z00);
        }
        {
            float xs = ldsf(aEc0 + (uint32_t)(i1 * STRIDE * 4));
            float x2 = ldsf(aAc0 + (uint32_t)(i1 * STRIDE * 4));
            float kr = (i1 == c0) ? 1.f : 0.f;
            p0[i1] = kr + xs + 0.5f * x2;
            stsf(aEc0 + (uint32_t)(i1 * STRIDE * 4),
                 kr * (1.f / 720.f) + xs * (1.f / 5040.f) + x2 * (1.f / 40320.f));
            stsf(aAc0 + (uint32_t)(i1 * STRIDE * 4), z01);
        }
        {
            float xs = ldsf(aEc1 + (uint32_t)(i0 * STRIDE * 4));
            float x2 = ldsf(aAc1 + (uint32_t)(i0 * STRIDE * 4));
            float kr = (i0 == c1) ? 1.f : 0.f;
            p1[i0] = kr + xs + 0.5f * x2;
            stsf(aEc1 + (uint32_t)(i0 * STRIDE * 4),
                 kr * (1.f / 720.f) + xs * (1.f / 5040.f) + x2 * (1.f / 40320.f));
            stsf(aAc1 + (uint32_t)(i0 * STRIDE * 4), z10);
        }
        {
            float xs = ldsf(aEc1 + (uint32_t)(i1 * STRIDE * 4));
            float x2 = ldsf(aAc1 + (uint32_t)(i1 * STRIDE * 4));
            float kr = (i1 == c1) ? 1.f : 0.f;
            p1[i1] = kr + xs + 0.5f * x2;
            stsf(aEc1 + (uint32_t)(i1 * STRIDE * 4),
                 kr * (1.f / 720.f) + xs * (1.f / 5040.f) + x2 * (1.f / 40320.f));
            stsf(aAc1 + (uint32_t)(i1 * STRIDE * 4), z11);
        }
    }
    __syncwarp();

    // ---- stage 2: U = B2 * Z   (A-op = E = B2, B-op = Z cols from A)
    mm_s(aE, aAc0, aAc1, acc0, acc1);
    __syncwarp();   // mm reads of E complete before overwrite
    // E := V = U + B1,  B1 = 168*B2 - 0.075*I + B0/120.
#pragma unroll
    for (int p = 0; p < 16; ++p) {
        const int i0 = 2 * p, i1 = 2 * p + 1;
        float u00, u01, u10, u11;
        upk2(u00, u01, acc0[p]); upk2(u10, u11, acc1[p]);
        {
            float b2 = ldsf(aEc0 + (uint32_t)(i0 * STRIDE * 4));
            float kr = (i0 == c0) ? 1.f : 0.f;
            stsf(aEc0 + (uint32_t)(i0 * STRIDE * 4),
                 u00 + 168.f * b2 - 0.075f * kr + p0[i0] * (1.f / 120.f));
        }
        {
            float b2 = ldsf(aEc0 + (uint32_t)(i1 * STRIDE * 4));
            float kr = (i1 == c0) ? 1.f : 0.f;
            stsf(aEc0 + (uint32_t)(i1 * STRIDE * 4),
                 u01 + 168.f * b2 - 0.075f * kr + p0[i1] * (1.f / 120.f));
        }
        {
            float b2 = ldsf(aEc1 + (uint32_t)(i0 * STRIDE * 4));
            float kr = (i0 == c1) ? 1.f : 0.f;
            stsf(aEc1 + (uint32_t)(i0 * STRIDE * 4),
                 u10 + 168.f * b2 - 0.075f * kr + p1[i0] * (1.f / 120.f));
        }
        {
            float b2 = ldsf(aEc1 + (uint32_t)(i1 * STRIDE * 4));
            float kr = (i1 == c1) ? 1.f : 0.f;
            stsf(aEc1 + (uint32_t)(i1 * STRIDE * 4),
                 u11 + 168.f * b2 - 0.075f * kr + p1[i1] * (1.f / 120.f));
        }
    }
    __syncwarp();

    // ---- stage 3: M2 = Z * V   (A-op = A = Z, B-op = V cols from E)
    mm_s(aA, aEc0, aEc1, acc0, acc1);
    // p := P = M2 + B0.
#pragma unroll
    for (int p = 0; p < 16; ++p) {
        float m00, m01, m10, m11;
        upk2(m00, m01, acc0[p]); upk2(m10, m11, acc1[p]);
        p0[2 * p] += m00; p0[2 * p + 1] += m01;
        p1[2 * p] += m10; p1[2 * p + 1] += m11;
    }
    __syncwarp();   // mm reads of A (Z) complete before overwrite
    if (total > 4) {
#pragma unroll
        for (int i = 0; i < 32; ++i) {
            stsf(aAc0 + (uint32_t)(i * STRIDE * 4), p0[i]);
            stsf(aAc1 + (uint32_t)(i * STRIDE * 4), p1[i]);
        }
    }
    __syncwarp();

    // ---- squarings: P = P * P   (A-op = A, B-op = P cols from A)
    for (int s = 4; s < total; ++s) {
        mm_s(aA, aAc0, aAc1, acc0, acc1);
#pragma unroll
        for (int p = 0; p < 16; ++p) {
            upk2(p0[2 * p], p0[2 * p + 1], acc0[p]);
            upk2(p1[2 * p], p1[2 * p + 1], acc1[p]);
        }
        __syncwarp();
        if (s < total - 1) {
#pragma unroll
            for (int i = 0; i < 32; ++i) {
                stsf(aAc0 + (uint32_t)(i * STRIDE * 4), p0[i]);
                stsf(aAc1 + (uint32_t)(i * STRIDE * 4), p1[i]);
            }
        }
        __syncwarp();
    }

    if (alive) {
        float* dst = out + (size_t)mat * 1024;
#pragma unroll
        for (int i = 0; i < 32; ++i) {
            dst[i * 32 + c0] = p0[i];
            dst[i * 32 + c1] = p1[i];
        }
    }
}

extern "C" void kernel_launch(void* const* d_in, const int* in_sizes, int n_in,
                              void* d_out, int out_size) {
    (void)n_in; (void)out_size;
    const float* x = (const float*)d_in[0];
    float* out = (float*)d_out;
    const int B = in_sizes[0] / 1024;
    const int ctas = (B + 1) / 2;
    ExpEig_52553219834314_kernel<<<ctas, 32>>>(x, out, B);
}